// round 11
// baseline (speedup 1.0000x reference)
#include <cuda_runtime.h>
#include <cstdint>
#include <cfloat>
#include <math.h>

#define BB   2
#define NNN  2048
#define DIMM 1024
#define HHH  16
#define DHH  64
#define MMM  16
#define JJJ  2064   // M + N
#define J4   516    // JJJ/4
#define ROTD 32

// d_out layout (floats): out | pre | post
#define OFF_OUT  0
#define OFF_PRE  (BB*NNN*DIMM)
#define OFF_POST (OFF_PRE + BB*HHH*NNN*JJJ)

// ---- scratch (device globals; allocation-free rule) ----
__device__ float g_q  [BB*HHH*NNN*DHH];                 // (b,h,i,d)
__device__ float g_k  [BB*HHH*JJJ*DHH];                 // (b,h,j,d)
__device__ float g_vT [BB*HHH*DHH*JJJ];                 // (b,h,d,j)
__device__ float g_attn2[(size_t)BB*HHH*NNN*JJJ];       // mixed logits, then post-mixed attn
__device__ float g_oh [BB*NNN*HHH*DHH];                 // (b,i, h*64+d)
__device__ float g_stat_m  [BB*HHH*NNN];
__device__ float g_stat_inv[BB*HHH*NNN];

// ---------------- tf32 mma helpers ----------------
__device__ __forceinline__ uint32_t f2tf(float f) {
    uint32_t u; asm("cvt.rna.tf32.f32 %0, %1;" : "=r"(u) : "f"(f)); return u;
}
__device__ __forceinline__ uint4 f2tf4(float4 v) {
    uint4 u; u.x = f2tf(v.x); u.y = f2tf(v.y); u.z = f2tf(v.z); u.w = f2tf(v.w); return u;
}
__device__ __forceinline__ void mma8(float c[4], const uint32_t a[4], uint32_t b0, uint32_t b1) {
    asm volatile(
        "mma.sync.aligned.m16n8k8.row.col.f32.tf32.tf32.f32 "
        "{%0,%1,%2,%3},{%4,%5,%6,%7},{%8,%9},{%0,%1,%2,%3};"
        : "+f"(c[0]), "+f"(c[1]), "+f"(c[2]), "+f"(c[3])
        : "r"(a[0]), "r"(a[1]), "r"(a[2]), "r"(a[3]), "r"(b0), "r"(b1));
}

// Warp computes a 32x(NT*8) C tile; smem tiles hold PRE-CONVERTED tf32 bits.
template<int S, int NT>
__device__ __forceinline__ void warp_mma(const uint32_t* As, const uint32_t* Bs,
                                         int mw, int nw, int kc, int lane,
                                         float acc[2][NT][4]) {
    const int r = lane >> 2, q = lane & 3;
    for (int k0 = 0; k0 < kc; k0 += 8) {
        uint32_t a[2][4];
#pragma unroll
        for (int mt = 0; mt < 2; mt++) {
            const uint32_t* p = As + (mw + mt*16 + r) * S + k0 + q;
            a[mt][0] = p[0];
            a[mt][1] = p[8*S];
            a[mt][2] = p[4];
            a[mt][3] = p[8*S + 4];
        }
#pragma unroll
        for (int nt = 0; nt < NT; nt++) {
            const uint32_t* p = Bs + (nw + nt*8 + r) * S + k0 + q;
            uint32_t b0 = p[0], b1 = p[4];
            mma8(acc[0][nt], a[0], b0, b1);
            mma8(acc[1][nt], a[1], b0, b1);
        }
    }
}

// ---------------- K1: QKV projection + rotary (+ memfill fold) ----------------
// grid (24, 33): y<32 = 128-row m-tiles; y==32 = memory K/V broadcast. block 256.
__global__ __launch_bounds__(256)
void k_qkv(const float* __restrict__ x,
           const float* __restrict__ Wq, const float* __restrict__ Wk,
           const float* __restrict__ Wv, const float* __restrict__ rot,
           const float* __restrict__ mem_k, const float* __restrict__ mem_v) {
    __shared__ uint32_t As[128*36];
    __shared__ uint32_t Bs[128*36];
    const int tid = threadIdx.x, lane = tid & 31, w = tid >> 5;

    if (blockIdx.y == 32) {
        const int total = BB*HHH*MMM*DHH;     // 32768
        for (int idx = blockIdx.x*256 + tid; idx < total; idx += 24*256) {
            int d = idx & 63, j = (idx >> 6) & 15, bh = idx >> 10;
            int h = bh & 15;
            g_k [((size_t)bh*JJJ + j)*DHH + d] = mem_k[(h*MMM + j)*DHH + d];
            g_vT[((size_t)bh*DHH + d)*JJJ + j] = mem_v[(h*MMM + j)*DHH + d];
        }
        return;
    }

    const int mbase = blockIdx.y * 128;
    const int ntile = blockIdx.x;
    const int which = ntile >> 3;                  // 0=q 1=k 2=v
    const float* W = (which == 0) ? Wq : (which == 1 ? Wk : Wv);
    const int nlocal = (ntile & 7) * 128;
    const int mw = (w >> 1)*32, nwarp = (w & 1)*64;
    const int h = ((ntile & 7) << 1) + (w & 1);

    float acc[2][8][4];
#pragma unroll
    for (int a = 0; a < 2; a++)
#pragma unroll
        for (int b = 0; b < 8; b++)
#pragma unroll
            for (int c = 0; c < 4; c++) acc[a][b][c] = 0.f;

    for (int kc = 0; kc < 1024; kc += 32) {
#pragma unroll
        for (int t = 0; t < 4; t++) {
            int idx = tid + t*256;
            int row = idx >> 3, col4 = (idx & 7) * 4;
            float4 va = *(const float4*)&x[(size_t)(mbase + row)*1024 + kc + col4];
            *(uint4*)&As[row*36 + col4] = f2tf4(va);
            float4 vb = *(const float4*)&W[(size_t)(nlocal + row)*1024 + kc + col4];
            *(uint4*)&Bs[row*36 + col4] = f2tf4(vb);
        }
        __syncthreads();
        warp_mma<36, 8>(As, Bs, mw, nwarp, 32, lane, acc);
        __syncthreads();
    }

    const int r = lane >> 2, q = lane & 3;

#pragma unroll
    for (int mt = 0; mt < 2; mt++) {
#pragma unroll
        for (int ci = 0; ci < 4; ci++) {
            int row = mbase + mw + mt*16 + r + ((ci & 2) ? 8 : 0);
            int b = row >> 11, i = row & 2047;
            if (which < 2) {
#pragma unroll
                for (int nt = 0; nt < 2; nt++) {
                    int d = nt*8 + 2*q + (ci & 1);
                    float lo = acc[mt][nt][ci];
                    float hi = acc[mt][nt + 2][ci];
                    float ang = rot[i*ROTD + d];
                    float cs, sn;
                    __sincosf(ang, &sn, &cs);
                    acc[mt][nt][ci]     = lo*cs - hi*sn;
                    acc[mt][nt + 2][ci] = hi*cs + lo*sn;
                }
            }
#pragma unroll
            for (int nt = 0; nt < 8; nt++) {
                int d = nt*8 + 2*q + (ci & 1);
                float v = acc[mt][nt][ci];
                size_t bh = (size_t)(b*16 + h);
                if (which == 0)      g_q [(bh*NNN + i)*DHH + d] = v;
                else if (which == 1) g_k [(bh*JJJ + i + 16)*DHH + d] = v;
                else                 g_vT[(bh*DHH + d)*JJJ + (i + 16)] = v;
            }
        }
    }
}

// ---------------- K2: dots = scale * q @ k^T -> pre ----------------
__global__ __launch_bounds__(256)
void k_dots(float* __restrict__ pre) {
    __shared__ uint32_t As[128*36];
    __shared__ uint32_t Bs[128*36];
    const int tid = threadIdx.x, lane = tid & 31, w = tid >> 5;
    const int bh = blockIdx.z;
    const int mbase = blockIdx.y * 128;
    const int jbase = blockIdx.x * 128;
    const int mw = (w >> 1)*32, nwarp = (w & 1)*64;

    float acc[2][8][4];
#pragma unroll
    for (int a = 0; a < 2; a++)
#pragma unroll
        for (int b = 0; b < 8; b++)
#pragma unroll
            for (int c = 0; c < 4; c++) acc[a][b][c] = 0.f;

    for (int kc = 0; kc < 64; kc += 32) {
#pragma unroll
        for (int t = 0; t < 4; t++) {
            int idx = tid + t*256;
            int row = idx >> 3, col4 = (idx & 7) * 4;
            float4 va = *(const float4*)&g_q[((size_t)bh*NNN + mbase + row)*DHH + kc + col4];
            *(uint4*)&As[row*36 + col4] = f2tf4(va);
            int j = jbase + row;
            float4 vb = (j < JJJ)
                ? *(const float4*)&g_k[((size_t)bh*JJJ + j)*DHH + kc + col4]
                : make_float4(0.f, 0.f, 0.f, 0.f);
            *(uint4*)&Bs[row*36 + col4] = f2tf4(vb);
        }
        __syncthreads();
        warp_mma<36, 8>(As, Bs, mw, nwarp, 32, lane, acc);
        __syncthreads();
    }

    const int r = lane >> 2, q = lane & 3;
#pragma unroll
    for (int mt = 0; mt < 2; mt++)
#pragma unroll
        for (int ci = 0; ci < 4; ci++) {
            int row = mbase + mw + mt*16 + r + ((ci & 2) ? 8 : 0);
#pragma unroll
            for (int nt = 0; nt < 8; nt++) {
                int j = jbase + nwarp + nt*8 + 2*q + (ci & 1);
                if (j < JJJ)
                    pre[((size_t)bh*NNN + row)*JJJ + j] = acc[mt][nt][ci] * 0.125f;
            }
        }
}

// ---------------- M1: mix1 + online softmax stats ----------------
__global__ __launch_bounds__(512, 2)
void k_mix1(const float* __restrict__ pre, const float* __restrict__ preP) {
    __shared__ float4 sC[16][128];
    const int bx = blockIdx.x;
    const int b = bx >> 11, i = bx & 2047;
    const int tid = threadIdx.x, lane = tid & 31, w = tid >> 5;
    const int nvalid = i + 17;
    const int nv4 = (nvalid + 3) >> 2;

    float pk[16];
#pragma unroll
    for (int h = 0; h < 16; h++) pk[h] = __ldg(&preP[h*16 + w]);

    const float4* src = (const float4*)&pre[(((size_t)(b*16 + w))*NNN + i)*JJJ];
    float4* dst = (float4*)&g_attn2[(((size_t)(b*16 + w))*NNN + i)*JJJ];

    float m = -FLT_MAX, s = 0.f;

    for (int base = 0; base < nv4; base += 128) {
        int c4 = min(128, nv4 - base);
        for (int c = lane; c < c4; c += 32) sC[w][c] = src[base + c];
        __syncthreads();
        for (int c = lane; c < c4; c += 32) {
            float4 mx = make_float4(0.f, 0.f, 0.f, 0.f);
#pragma unroll
            for (int h = 0; h < 16; h++) {
                float4 d = sC[h][c];
                mx.x += d.x*pk[h]; mx.y += d.y*pk[h];
                mx.z += d.z*pk[h]; mx.w += d.w*pk[h];
            }
            dst[base + c] = mx;
            int j0 = 4*(base + c);
            float v0 = mx.x;
            float v1 = (j0 + 1 < nvalid) ? mx.y : -FLT_MAX;
            float v2 = (j0 + 2 < nvalid) ? mx.z : -FLT_MAX;
            float v3 = (j0 + 3 < nvalid) ? mx.w : -FLT_MAX;
            float cm = fmaxf(fmaxf(v0, v1), fmaxf(v2, v3));
            float mn = fmaxf(m, cm);
            float add = __expf(v0 - mn) + __expf(v1 - mn) + __expf(v2 - mn) + __expf(v3 - mn);
            s = s*__expf(m - mn) + add;
            m = mn;
        }
        __syncthreads();
    }

#pragma unroll
    for (int o = 16; o > 0; o >>= 1) {
        float om = __shfl_xor_sync(0xffffffffu, m, o);
        float os = __shfl_xor_sync(0xffffffffu, s, o);
        float mn = fmaxf(m, om);
        s = s*__expf(m - mn) + os*__expf(om - mn);
        m = mn;
    }
    if (lane == 0) {
        g_stat_m  [(size_t)(b*16 + w)*NNN + i] = m;
        g_stat_inv[(size_t)(b*16 + w)*NNN + i] = 1.0f / s;
    }
}

// ---------------- M2: exp + post + mix2 -> attn2 (barrier-free streaming) ----------------
// grid 4096 (b*2048+i), block 256. Each thread owns float4 columns; acc[16] in regs.
__global__ __launch_bounds__(256, 2)
void k_mix2(float* __restrict__ post, const float* __restrict__ postP) {
    __shared__ float sM[16];          // per-head max
    __shared__ float sI[16];          // per-head 1/sum
    __shared__ float sCk[16][16];     // ck[h][w] = inv[h]*postP[h][w]
    const int bx = blockIdx.x;
    const int b = bx >> 11, i = bx & 2047;
    const int tid = threadIdx.x;
    const int nvalid = i + 17;
    const int nv4 = (nvalid + 3) >> 2;

    if (tid < 16) {
        sM[tid] = g_stat_m  [(size_t)(b*16 + tid)*NNN + i];
        sI[tid] = g_stat_inv[(size_t)(b*16 + tid)*NNN + i];
    }
    __syncthreads();
    {
        int h = tid >> 4, w = tid & 15;
        sCk[h][w] = sI[h] * __ldg(&postP[h*16 + w]);
    }
    __syncthreads();

    const size_t rowStride = (size_t)NNN * JJJ;          // between heads
    float* mbase0 = g_attn2 + (((size_t)(b*16))*NNN + i)*JJJ;
    float* pbase0 = post    + (((size_t)(b*16))*NNN + i)*JJJ;

    for (int c = tid; c < nv4; c += 256) {
        const int j0 = 4*c;
        const bool full = (j0 + 3 < nvalid);
        float4 acc[16];
#pragma unroll
        for (int w = 0; w < 16; w++) acc[w] = make_float4(0.f, 0.f, 0.f, 0.f);

#pragma unroll
        for (int h = 0; h < 16; h++) {
            float4 v = *(float4*)(mbase0 + h*rowStride + j0);
            const float mm = sM[h];
            float4 e;
            e.x = __expf(v.x - mm);
            e.y = (full || j0 + 1 < nvalid) ? __expf(v.y - mm) : 0.f;
            e.z = (full || j0 + 2 < nvalid) ? __expf(v.z - mm) : 0.f;
            e.w = full ? __expf(v.w - mm) : 0.f;
            const float inv = sI[h];
            *(float4*)(pbase0 + h*rowStride + j0) =
                make_float4(e.x*inv, e.y*inv, e.z*inv, e.w*inv);
#pragma unroll
            for (int w = 0; w < 16; w++) {
                const float ck = sCk[h][w];
                acc[w].x += e.x*ck; acc[w].y += e.y*ck;
                acc[w].z += e.z*ck; acc[w].w += e.w*ck;
            }
        }
#pragma unroll
        for (int w = 0; w < 16; w++)
            *(float4*)(mbase0 + w*rowStride + j0) = acc[w];
    }

    // tails (division-free): post zeros to JJJ; attn2 zeros to k_av's read bound
    const float4 z4 = make_float4(0.f, 0.f, 0.f, 0.f);
    int kcend = ((((i >> 7) << 7) + 144 + 47) / 48) * 48;
    if (kcend > JJJ) kcend = JJJ;
    const int kc4 = kcend >> 2;
#pragma unroll 1
    for (int h = 0; h < 16; h++) {
        float4* pp = (float4*)(pbase0 + h*rowStride);
        for (int c = nv4 + tid; c < J4; c += 256) pp[c] = z4;
        float4* aa = (float4*)(mbase0 + h*rowStride);
        for (int c = nv4 + tid; c < kc4; c += 256) aa[c] = z4;
    }
}

// ---------------- K4: out_heads = attn2 @ v ----------------
// grid (16 m-tiles of 128, 32 bh). block 256 = 8 warps (4m x 2n), 32x32 each.
__global__ __launch_bounds__(256)
void k_av() {
    __shared__ uint32_t As[128*52];
    __shared__ uint32_t Bs[64*52];
    const int tid = threadIdx.x, lane = tid & 31, w = tid >> 5;
    const int mbase = blockIdx.x * 128;
    const int bh = blockIdx.y;
    const int b = bh >> 4, h = bh & 15;
    const int mw = (w >> 1)*32, nw = (w & 1)*32;

    float acc[2][4][4];
#pragma unroll
    for (int a = 0; a < 2; a++)
#pragma unroll
        for (int bb = 0; bb < 4; bb++)
#pragma unroll
            for (int c = 0; c < 4; c++) acc[a][bb][c] = 0.f;

    const float* Abase = &g_attn2[((size_t)bh*NNN + mbase)*JJJ];
    const float* Bbase = &g_vT[(size_t)bh*DHH*JJJ];

    int kcend = mbase + 144;
    kcend = ((kcend + 47) / 48) * 48;
    if (kcend > JJJ) kcend = JJJ;

    for (int kc = 0; kc < kcend; kc += 48) {
#pragma unroll
        for (int t = 0; t < 6; t++) {
            int idx = tid + t*256;
            int row = idx / 12, col4 = (idx % 12) * 4;
            float4 va = *(const float4*)&Abase[(size_t)row*JJJ + kc + col4];
            *(uint4*)&As[row*52 + col4] = f2tf4(va);
        }
#pragma unroll
        for (int t = 0; t < 3; t++) {
            int idx = tid + t*256;
            int row = idx / 12, col4 = (idx % 12) * 4;
            float4 vb = *(const float4*)&Bbase[(size_t)row*JJJ + kc + col4];
            *(uint4*)&Bs[row*52 + col4] = f2tf4(vb);
        }
        __syncthreads();
        warp_mma<52, 4>(As, Bs, mw, nw, 48, lane, acc);
        __syncthreads();
    }

    const int r = lane >> 2, q = lane & 3;
#pragma unroll
    for (int mt = 0; mt < 2; mt++)
#pragma unroll
        for (int ci = 0; ci < 4; ci++) {
            int row = mbase + mw + mt*16 + r + ((ci & 2) ? 8 : 0);
#pragma unroll
            for (int nt = 0; nt < 4; nt++) {
                int d = nw + nt*8 + 2*q + (ci & 1);
                g_oh[((size_t)(b*NNN + row))*DIMM + h*DHH + d] = acc[mt][nt][ci];
            }
        }
}

// ---------------- K5: out = oh @ Wo^T + bo ----------------
// grid (8, 32): 128-wide n-tiles, 128-row m-tiles. block 256, warps 32x64.
__global__ __launch_bounds__(256)
void k_outproj(const float* __restrict__ Wo, const float* __restrict__ bo,
               float* __restrict__ out) {
    __shared__ uint32_t As[128*36];
    __shared__ uint32_t Bs[128*36];
    const int tid = threadIdx.x, lane = tid & 31, w = tid >> 5;
    const int mbase = blockIdx.y * 128;
    const int nbase = blockIdx.x * 128;
    const int mw = (w >> 1)*32, nwarp = (w & 1)*64;

    float acc[2][8][4];
#pragma unroll
    for (int a = 0; a < 2; a++)
#pragma unroll
        for (int b = 0; b < 8; b++)
#pragma unroll
            for (int c = 0; c < 4; c++) acc[a][b][c] = 0.f;

    for (int kc = 0; kc < 1024; kc += 32) {
#pragma unroll
        for (int t = 0; t < 4; t++) {
            int idx = tid + t*256;
            int row = idx >> 3, col4 = (idx & 7) * 4;
            float4 va = *(const float4*)&g_oh[(size_t)(mbase + row)*1024 + kc + col4];
            *(uint4*)&As[row*36 + col4] = f2tf4(va);
            float4 vb = *(const float4*)&Wo[(size_t)(nbase + row)*1024 + kc + col4];
            *(uint4*)&Bs[row*36 + col4] = f2tf4(vb);
        }
        __syncthreads();
        warp_mma<36, 8>(As, Bs, mw, nwarp, 32, lane, acc);
        __syncthreads();
    }

    const int r = lane >> 2, q = lane & 3;
#pragma unroll
    for (int mt = 0; mt < 2; mt++)
#pragma unroll
        for (int ci = 0; ci < 4; ci++) {
            int row = mbase + mw + mt*16 + r + ((ci & 2) ? 8 : 0);
#pragma unroll
            for (int nt = 0; nt < 8; nt++) {
                int col = nbase + nwarp + nt*8 + 2*q + (ci & 1);
                out[(size_t)row*1024 + col] = acc[mt][nt][ci] + bo[col];
            }
        }
}

// ---------------- launch ----------------
extern "C" void kernel_launch(void* const* d_in, const int* in_sizes, int n_in,
                              void* d_out, int out_size) {
    const float* x     = (const float*)d_in[0];
    const float* rot   = (const float*)d_in[1];
    const float* Wq    = (const float*)d_in[2];
    const float* Wk    = (const float*)d_in[3];
    const float* Wv    = (const float*)d_in[4];
    const float* mem_k = (const float*)d_in[5];
    const float* mem_v = (const float*)d_in[6];
    const float* preP  = (const float*)d_in[7];
    const float* postP = (const float*)d_in[8];
    const float* Wo    = (const float*)d_in[9];
    const float* bo    = (const float*)d_in[10];

    float* out  = (float*)d_out;
    float* pre  = out + OFF_PRE;
    float* post = out + OFF_POST;

    k_qkv<<<dim3(24, 33), 256>>>(x, Wq, Wk, Wv, rot, mem_k, mem_v);
    k_dots<<<dim3(17, 16, 32), 256>>>(pre);
    k_mix1<<<BB*NNN, 512>>>(pre, preP);
    k_mix2<<<BB*NNN, 256>>>(post, postP);
    k_av<<<dim3(16, 32), 256>>>();
    k_outproj<<<dim3(8, 32), 256>>>(Wo, bo, out);
}

// round 12
// speedup vs baseline: 1.0609x; 1.0609x over previous
#include <cuda_runtime.h>
#include <cstdint>
#include <cfloat>
#include <math.h>

#define BB   2
#define NNN  2048
#define DIMM 1024
#define HHH  16
#define DHH  64
#define MMM  16
#define JJJ  2064   // M + N
#define J4   516    // JJJ/4
#define ROTD 32

// d_out layout (floats): out | pre | post
#define OFF_OUT  0
#define OFF_PRE  (BB*NNN*DIMM)
#define OFF_POST (OFF_PRE + BB*HHH*NNN*JJJ)

// ---- scratch (device globals; allocation-free rule) ----
__device__ float g_q  [BB*HHH*NNN*DHH];                 // (b,h,i,d)
__device__ float g_k  [BB*HHH*JJJ*DHH];                 // (b,h,j,d)
__device__ float g_vT [BB*HHH*DHH*JJJ];                 // (b,h,d,j)
__device__ float g_attn2[(size_t)BB*HHH*NNN*JJJ];       // mixed logits, then post-mixed attn
__device__ float g_oh [BB*NNN*HHH*DHH];                 // (b,i, h*64+d)
__device__ float g_stat_m  [BB*HHH*NNN];
__device__ float g_stat_inv[BB*HHH*NNN];

// ---------------- tf32 mma helpers ----------------
__device__ __forceinline__ uint32_t f2tf(float f) {
    uint32_t u; asm("cvt.rna.tf32.f32 %0, %1;" : "=r"(u) : "f"(f)); return u;
}
__device__ __forceinline__ uint4 f2tf4(float4 v) {
    uint4 u; u.x = f2tf(v.x); u.y = f2tf(v.y); u.z = f2tf(v.z); u.w = f2tf(v.w); return u;
}
__device__ __forceinline__ void mma8(float c[4], const uint32_t a[4], uint32_t b0, uint32_t b1) {
    asm volatile(
        "mma.sync.aligned.m16n8k8.row.col.f32.tf32.tf32.f32 "
        "{%0,%1,%2,%3},{%4,%5,%6,%7},{%8,%9},{%0,%1,%2,%3};"
        : "+f"(c[0]), "+f"(c[1]), "+f"(c[2]), "+f"(c[3])
        : "r"(a[0]), "r"(a[1]), "r"(a[2]), "r"(a[3]), "r"(b0), "r"(b1));
}

// Warp computes a 32x(NT*8) C tile; smem tiles hold PRE-CONVERTED tf32 bits.
template<int S, int NT>
__device__ __forceinline__ void warp_mma(const uint32_t* As, const uint32_t* Bs,
                                         int mw, int nw, int kc, int lane,
                                         float acc[2][NT][4]) {
    const int r = lane >> 2, q = lane & 3;
    for (int k0 = 0; k0 < kc; k0 += 8) {
        uint32_t a[2][4];
#pragma unroll
        for (int mt = 0; mt < 2; mt++) {
            const uint32_t* p = As + (mw + mt*16 + r) * S + k0 + q;
            a[mt][0] = p[0];
            a[mt][1] = p[8*S];
            a[mt][2] = p[4];
            a[mt][3] = p[8*S + 4];
        }
#pragma unroll
        for (int nt = 0; nt < NT; nt++) {
            const uint32_t* p = Bs + (nw + nt*8 + r) * S + k0 + q;
            uint32_t b0 = p[0], b1 = p[4];
            mma8(acc[0][nt], a[0], b0, b1);
            mma8(acc[1][nt], a[1], b0, b1);
        }
    }
}

#define TILE_U (128*36)   // one 128x32 tile (S=36) in uint32

// ---------------- K1: QKV projection + rotary (+ memfill fold), double-buffered ----------------
// grid (24, 33): y<32 = 128-row m-tiles; y==32 = memory K/V broadcast. block 256.
// dyn smem: 2 stages x (A+B) = 4*TILE_U uint32 = 72KB.
__global__ __launch_bounds__(256, 2)
void k_qkv(const float* __restrict__ x,
           const float* __restrict__ Wq, const float* __restrict__ Wk,
           const float* __restrict__ Wv, const float* __restrict__ rot,
           const float* __restrict__ mem_k, const float* __restrict__ mem_v) {
    extern __shared__ uint32_t smq[];
    uint32_t* Asb = smq;                 // [2][TILE_U]
    uint32_t* Bsb = smq + 2*TILE_U;      // [2][TILE_U]
    const int tid = threadIdx.x, lane = tid & 31, w = tid >> 5;

    if (blockIdx.y == 32) {
        const int total = BB*HHH*MMM*DHH;     // 32768
        for (int idx = blockIdx.x*256 + tid; idx < total; idx += 24*256) {
            int d = idx & 63, j = (idx >> 6) & 15, bh = idx >> 10;
            int h = bh & 15;
            g_k [((size_t)bh*JJJ + j)*DHH + d] = mem_k[(h*MMM + j)*DHH + d];
            g_vT[((size_t)bh*DHH + d)*JJJ + j] = mem_v[(h*MMM + j)*DHH + d];
        }
        return;
    }

    const int mbase = blockIdx.y * 128;
    const int ntile = blockIdx.x;
    const int which = ntile >> 3;                  // 0=q 1=k 2=v
    const float* W = (which == 0) ? Wq : (which == 1 ? Wk : Wv);
    const int nlocal = (ntile & 7) * 128;
    const int mw = (w >> 1)*32, nwarp = (w & 1)*64;
    const int h = ((ntile & 7) << 1) + (w & 1);

    float acc[2][8][4];
#pragma unroll
    for (int a = 0; a < 2; a++)
#pragma unroll
        for (int b = 0; b < 8; b++)
#pragma unroll
            for (int c = 0; c < 4; c++) acc[a][b][c] = 0.f;

    // preload stage 0 (kc = 0)
#pragma unroll
    for (int t = 0; t < 4; t++) {
        int idx = tid + t*256;
        int row = idx >> 3, col4 = (idx & 7) * 4;
        float4 va = *(const float4*)&x[(size_t)(mbase + row)*1024 + col4];
        *(uint4*)&Asb[row*36 + col4] = f2tf4(va);
        float4 vb = *(const float4*)&W[(size_t)(nlocal + row)*1024 + col4];
        *(uint4*)&Bsb[row*36 + col4] = f2tf4(vb);
    }
    __syncthreads();

    int s = 0;
    for (int kc = 0; kc < 1024; kc += 32) {
        float4 pa[4], pb[4];
        const bool more = (kc + 32 < 1024);
        if (more) {
#pragma unroll
            for (int t = 0; t < 4; t++) {
                int idx = tid + t*256;
                int row = idx >> 3, col4 = (idx & 7) * 4;
                pa[t] = *(const float4*)&x[(size_t)(mbase + row)*1024 + kc + 32 + col4];
                pb[t] = *(const float4*)&W[(size_t)(nlocal + row)*1024 + kc + 32 + col4];
            }
        }
        warp_mma<36, 8>(Asb + s*TILE_U, Bsb + s*TILE_U, mw, nwarp, 32, lane, acc);
        if (more) {
            uint32_t* An = Asb + (s ^ 1)*TILE_U;
            uint32_t* Bn = Bsb + (s ^ 1)*TILE_U;
#pragma unroll
            for (int t = 0; t < 4; t++) {
                int idx = tid + t*256;
                int row = idx >> 3, col4 = (idx & 7) * 4;
                *(uint4*)&An[row*36 + col4] = f2tf4(pa[t]);
                *(uint4*)&Bn[row*36 + col4] = f2tf4(pb[t]);
            }
        }
        __syncthreads();
        s ^= 1;
    }

    const int r = lane >> 2, q = lane & 3;

#pragma unroll
    for (int mt = 0; mt < 2; mt++) {
#pragma unroll
        for (int ci = 0; ci < 4; ci++) {
            int row = mbase + mw + mt*16 + r + ((ci & 2) ? 8 : 0);
            int b = row >> 11, i = row & 2047;
            if (which < 2) {
#pragma unroll
                for (int nt = 0; nt < 2; nt++) {
                    int d = nt*8 + 2*q + (ci & 1);
                    float lo = acc[mt][nt][ci];
                    float hi = acc[mt][nt + 2][ci];
                    float ang = rot[i*ROTD + d];
                    float cs, sn;
                    __sincosf(ang, &sn, &cs);
                    acc[mt][nt][ci]     = lo*cs - hi*sn;
                    acc[mt][nt + 2][ci] = hi*cs + lo*sn;
                }
            }
#pragma unroll
            for (int nt = 0; nt < 8; nt++) {
                int d = nt*8 + 2*q + (ci & 1);
                float v = acc[mt][nt][ci];
                size_t bh = (size_t)(b*16 + h);
                if (which == 0)      g_q [(bh*NNN + i)*DHH + d] = v;
                else if (which == 1) g_k [(bh*JJJ + i + 16)*DHH + d] = v;
                else                 g_vT[(bh*DHH + d)*JJJ + (i + 16)] = v;
            }
        }
    }
}

// ---------------- K2: dots = scale * q @ k^T -> pre ----------------
__global__ __launch_bounds__(256)
void k_dots(float* __restrict__ pre) {
    __shared__ uint32_t As[128*36];
    __shared__ uint32_t Bs[128*36];
    const int tid = threadIdx.x, lane = tid & 31, w = tid >> 5;
    const int bh = blockIdx.z;
    const int mbase = blockIdx.y * 128;
    const int jbase = blockIdx.x * 128;
    const int mw = (w >> 1)*32, nwarp = (w & 1)*64;

    float acc[2][8][4];
#pragma unroll
    for (int a = 0; a < 2; a++)
#pragma unroll
        for (int b = 0; b < 8; b++)
#pragma unroll
            for (int c = 0; c < 4; c++) acc[a][b][c] = 0.f;

    for (int kc = 0; kc < 64; kc += 32) {
#pragma unroll
        for (int t = 0; t < 4; t++) {
            int idx = tid + t*256;
            int row = idx >> 3, col4 = (idx & 7) * 4;
            float4 va = *(const float4*)&g_q[((size_t)bh*NNN + mbase + row)*DHH + kc + col4];
            *(uint4*)&As[row*36 + col4] = f2tf4(va);
            int j = jbase + row;
            float4 vb = (j < JJJ)
                ? *(const float4*)&g_k[((size_t)bh*JJJ + j)*DHH + kc + col4]
                : make_float4(0.f, 0.f, 0.f, 0.f);
            *(uint4*)&Bs[row*36 + col4] = f2tf4(vb);
        }
        __syncthreads();
        warp_mma<36, 8>(As, Bs, mw, nwarp, 32, lane, acc);
        __syncthreads();
    }

    const int r = lane >> 2, q = lane & 3;
#pragma unroll
    for (int mt = 0; mt < 2; mt++)
#pragma unroll
        for (int ci = 0; ci < 4; ci++) {
            int row = mbase + mw + mt*16 + r + ((ci & 2) ? 8 : 0);
#pragma unroll
            for (int nt = 0; nt < 8; nt++) {
                int j = jbase + nwarp + nt*8 + 2*q + (ci & 1);
                if (j < JJJ)
                    pre[((size_t)bh*NNN + row)*JJJ + j] = acc[mt][nt][ci] * 0.125f;
            }
        }
}

// ---------------- M1: mix1 + online softmax stats ----------------
__global__ __launch_bounds__(512, 2)
void k_mix1(const float* __restrict__ pre, const float* __restrict__ preP) {
    __shared__ float4 sC[16][128];
    const int bx = blockIdx.x;
    const int b = bx >> 11, i = bx & 2047;
    const int tid = threadIdx.x, lane = tid & 31, w = tid >> 5;
    const int nvalid = i + 17;
    const int nv4 = (nvalid + 3) >> 2;

    float pk[16];
#pragma unroll
    for (int h = 0; h < 16; h++) pk[h] = __ldg(&preP[h*16 + w]);

    const float4* src = (const float4*)&pre[(((size_t)(b*16 + w))*NNN + i)*JJJ];
    float4* dst = (float4*)&g_attn2[(((size_t)(b*16 + w))*NNN + i)*JJJ];

    float m = -FLT_MAX, s = 0.f;

    for (int base = 0; base < nv4; base += 128) {
        int c4 = min(128, nv4 - base);
        for (int c = lane; c < c4; c += 32) sC[w][c] = src[base + c];
        __syncthreads();
        for (int c = lane; c < c4; c += 32) {
            float4 mx = make_float4(0.f, 0.f, 0.f, 0.f);
#pragma unroll
            for (int h = 0; h < 16; h++) {
                float4 d = sC[h][c];
                mx.x += d.x*pk[h]; mx.y += d.y*pk[h];
                mx.z += d.z*pk[h]; mx.w += d.w*pk[h];
            }
            dst[base + c] = mx;
            int j0 = 4*(base + c);
            float v0 = mx.x;
            float v1 = (j0 + 1 < nvalid) ? mx.y : -FLT_MAX;
            float v2 = (j0 + 2 < nvalid) ? mx.z : -FLT_MAX;
            float v3 = (j0 + 3 < nvalid) ? mx.w : -FLT_MAX;
            float cm = fmaxf(fmaxf(v0, v1), fmaxf(v2, v3));
            float mn = fmaxf(m, cm);
            float add = __expf(v0 - mn) + __expf(v1 - mn) + __expf(v2 - mn) + __expf(v3 - mn);
            s = s*__expf(m - mn) + add;
            m = mn;
        }
        __syncthreads();
    }

#pragma unroll
    for (int o = 16; o > 0; o >>= 1) {
        float om = __shfl_xor_sync(0xffffffffu, m, o);
        float os = __shfl_xor_sync(0xffffffffu, s, o);
        float mn = fmaxf(m, om);
        s = s*__expf(m - mn) + os*__expf(om - mn);
        m = mn;
    }
    if (lane == 0) {
        g_stat_m  [(size_t)(b*16 + w)*NNN + i] = m;
        g_stat_inv[(size_t)(b*16 + w)*NNN + i] = 1.0f / s;
    }
}

// ---------------- M2: exp + post + mix2 -> attn2 (R10 chunked version) ----------------
__global__ __launch_bounds__(512, 2)
void k_mix2(float* __restrict__ post, const float* __restrict__ postP) {
    __shared__ float4 sC[16][128];
    __shared__ float sInv[16];
    const int bx = blockIdx.x;
    const int b = bx >> 11, i = bx & 2047;
    const int tid = threadIdx.x, lane = tid & 31, w = tid >> 5;
    const int nvalid = i + 17;
    const int nv4 = (nvalid + 3) >> 2;

    const float mmax = g_stat_m  [(size_t)(b*16 + w)*NNN + i];
    const float inv  = g_stat_inv[(size_t)(b*16 + w)*NNN + i];
    if (lane == 0) sInv[w] = inv;
    __syncthreads();

    float ck[16];
#pragma unroll
    for (int k = 0; k < 16; k++) ck[k] = sInv[k] * __ldg(&postP[k*16 + w]);

    float4* mrow = (float4*)&g_attn2[(((size_t)(b*16 + w))*NNN + i)*JJJ];
    float4* prow = (float4*)&post[(((size_t)(b*16 + w))*NNN + i)*JJJ];

    for (int base = 0; base < nv4; base += 128) {
        int c4 = min(128, nv4 - base);
        for (int c = lane; c < c4; c += 32) {
            float4 v = mrow[base + c];
            int j0 = 4*(base + c);
            float4 e;
            e.x = __expf(v.x - mmax);
            e.y = (j0 + 1 < nvalid) ? __expf(v.y - mmax) : 0.f;
            e.z = (j0 + 2 < nvalid) ? __expf(v.z - mmax) : 0.f;
            e.w = (j0 + 3 < nvalid) ? __expf(v.w - mmax) : 0.f;
            sC[w][c] = e;
            prow[base + c] = make_float4(e.x*inv, e.y*inv, e.z*inv, e.w*inv);
        }
        __syncthreads();
        for (int c = lane; c < c4; c += 32) {
            float4 acc = make_float4(0.f, 0.f, 0.f, 0.f);
#pragma unroll
            for (int k = 0; k < 16; k++) {
                float4 d = sC[k][c];
                acc.x += d.x*ck[k]; acc.y += d.y*ck[k];
                acc.z += d.z*ck[k]; acc.w += d.w*ck[k];
            }
            mrow[base + c] = acc;
        }
        __syncthreads();
    }

    // tails (division-free): post zeros to JJJ; attn2 zeros to k_av's read bound
    const float4 z4 = make_float4(0.f, 0.f, 0.f, 0.f);
    int kcend = ((((i >> 7) << 7) + 144 + 47) / 48) * 48;
    if (kcend > JJJ) kcend = JJJ;
    const int kc4 = kcend >> 2;
#pragma unroll 1
    for (int h = 0; h < 16; h++) {
        float4* pp = (float4*)&post[(((size_t)(b*16 + h))*NNN + i)*JJJ];
        for (int c = nv4 + tid; c < J4; c += 512) pp[c] = z4;
        float4* aa = (float4*)&g_attn2[(((size_t)(b*16 + h))*NNN + i)*JJJ];
        for (int c = nv4 + tid; c < kc4; c += 512) aa[c] = z4;
    }
}

// ---------------- K4: out_heads = attn2 @ v ----------------
// grid (16 m-tiles of 128, 32 bh). block 256 = 8 warps (4m x 2n), 32x32 each.
__global__ __launch_bounds__(256)
void k_av() {
    __shared__ uint32_t As[128*52];
    __shared__ uint32_t Bs[64*52];
    const int tid = threadIdx.x, lane = tid & 31, w = tid >> 5;
    const int mbase = blockIdx.x * 128;
    const int bh = blockIdx.y;
    const int b = bh >> 4, h = bh & 15;
    const int mw = (w >> 1)*32, nw = (w & 1)*32;

    float acc[2][4][4];
#pragma unroll
    for (int a = 0; a < 2; a++)
#pragma unroll
        for (int bb = 0; bb < 4; bb++)
#pragma unroll
            for (int c = 0; c < 4; c++) acc[a][bb][c] = 0.f;

    const float* Abase = &g_attn2[((size_t)bh*NNN + mbase)*JJJ];
    const float* Bbase = &g_vT[(size_t)bh*DHH*JJJ];

    int kcend = mbase + 144;
    kcend = ((kcend + 47) / 48) * 48;
    if (kcend > JJJ) kcend = JJJ;

    for (int kc = 0; kc < kcend; kc += 48) {
#pragma unroll
        for (int t = 0; t < 6; t++) {
            int idx = tid + t*256;
            int row = idx / 12, col4 = (idx % 12) * 4;
            float4 va = *(const float4*)&Abase[(size_t)row*JJJ + kc + col4];
            *(uint4*)&As[row*52 + col4] = f2tf4(va);
        }
#pragma unroll
        for (int t = 0; t < 3; t++) {
            int idx = tid + t*256;
            int row = idx / 12, col4 = (idx % 12) * 4;
            float4 vb = *(const float4*)&Bbase[(size_t)row*JJJ + kc + col4];
            *(uint4*)&Bs[row*52 + col4] = f2tf4(vb);
        }
        __syncthreads();
        warp_mma<52, 4>(As, Bs, mw, nw, 48, lane, acc);
        __syncthreads();
    }

    const int r = lane >> 2, q = lane & 3;
#pragma unroll
    for (int mt = 0; mt < 2; mt++)
#pragma unroll
        for (int ci = 0; ci < 4; ci++) {
            int row = mbase + mw + mt*16 + r + ((ci & 2) ? 8 : 0);
#pragma unroll
            for (int nt = 0; nt < 4; nt++) {
                int d = nw + nt*8 + 2*q + (ci & 1);
                g_oh[((size_t)(b*NNN + row))*DIMM + h*DHH + d] = acc[mt][nt][ci];
            }
        }
}

// ---------------- K5: out = oh @ Wo^T + bo, double-buffered ----------------
// grid (8, 32): 128-wide n-tiles, 128-row m-tiles. block 256, warps 32x64. dyn smem 72KB.
__global__ __launch_bounds__(256, 2)
void k_outproj(const float* __restrict__ Wo, const float* __restrict__ bo,
               float* __restrict__ out) {
    extern __shared__ uint32_t smo[];
    uint32_t* Asb = smo;
    uint32_t* Bsb = smo + 2*TILE_U;
    const int tid = threadIdx.x, lane = tid & 31, w = tid >> 5;
    const int mbase = blockIdx.y * 128;
    const int nbase = blockIdx.x * 128;
    const int mw = (w >> 1)*32, nwarp = (w & 1)*64;

    float acc[2][8][4];
#pragma unroll
    for (int a = 0; a < 2; a++)
#pragma unroll
        for (int b = 0; b < 8; b++)
#pragma unroll
            for (int c = 0; c < 4; c++) acc[a][b][c] = 0.f;

    // preload stage 0
#pragma unroll
    for (int t = 0; t < 4; t++) {
        int idx = tid + t*256;
        int row = idx >> 3, col4 = (idx & 7) * 4;
        float4 va = *(const float4*)&g_oh[(size_t)(mbase + row)*1024 + col4];
        *(uint4*)&Asb[row*36 + col4] = f2tf4(va);
        float4 vb = *(const float4*)&Wo[(size_t)(nbase + row)*1024 + col4];
        *(uint4*)&Bsb[row*36 + col4] = f2tf4(vb);
    }
    __syncthreads();

    int s = 0;
    for (int kc = 0; kc < 1024; kc += 32) {
        float4 pa[4], pb[4];
        const bool more = (kc + 32 < 1024);
        if (more) {
#pragma unroll
            for (int t = 0; t < 4; t++) {
                int idx = tid + t*256;
                int row = idx >> 3, col4 = (idx & 7) * 4;
                pa[t] = *(const float4*)&g_oh[(size_t)(mbase + row)*1024 + kc + 32 + col4];
                pb[t] = *(const float4*)&Wo[(size_t)(nbase + row)*1024 + kc + 32 + col4];
            }
        }
        warp_mma<36, 8>(Asb + s*TILE_U, Bsb + s*TILE_U, mw, nwarp, 32, lane, acc);
        if (more) {
            uint32_t* An = Asb + (s ^ 1)*TILE_U;
            uint32_t* Bn = Bsb + (s ^ 1)*TILE_U;
#pragma unroll
            for (int t = 0; t < 4; t++) {
                int idx = tid + t*256;
                int row = idx >> 3, col4 = (idx & 7) * 4;
                *(uint4*)&An[row*36 + col4] = f2tf4(pa[t]);
                *(uint4*)&Bn[row*36 + col4] = f2tf4(pb[t]);
            }
        }
        __syncthreads();
        s ^= 1;
    }

    const int r = lane >> 2, q = lane & 3;
#pragma unroll
    for (int mt = 0; mt < 2; mt++)
#pragma unroll
        for (int ci = 0; ci < 4; ci++) {
            int row = mbase + mw + mt*16 + r + ((ci & 2) ? 8 : 0);
#pragma unroll
            for (int nt = 0; nt < 8; nt++) {
                int col = nbase + nwarp + nt*8 + 2*q + (ci & 1);
                out[(size_t)row*1024 + col] = acc[mt][nt][ci] + bo[col];
            }
        }
}

// ---------------- launch ----------------
extern "C" void kernel_launch(void* const* d_in, const int* in_sizes, int n_in,
                              void* d_out, int out_size) {
    const float* x     = (const float*)d_in[0];
    const float* rot   = (const float*)d_in[1];
    const float* Wq    = (const float*)d_in[2];
    const float* Wk    = (const float*)d_in[3];
    const float* Wv    = (const float*)d_in[4];
    const float* mem_k = (const float*)d_in[5];
    const float* mem_v = (const float*)d_in[6];
    const float* preP  = (const float*)d_in[7];
    const float* postP = (const float*)d_in[8];
    const float* Wo    = (const float*)d_in[9];
    const float* bo    = (const float*)d_in[10];

    float* out  = (float*)d_out;
    float* pre  = out + OFF_PRE;
    float* post = out + OFF_POST;

    const int dynSmem = 4 * TILE_U * sizeof(uint32_t);   // 73728 bytes
    static bool attrDone = false;
    if (!attrDone) {
        cudaFuncSetAttribute(k_qkv, cudaFuncAttributeMaxDynamicSharedMemorySize, dynSmem);
        cudaFuncSetAttribute(k_outproj, cudaFuncAttributeMaxDynamicSharedMemorySize, dynSmem);
        attrDone = true;
    }

    k_qkv<<<dim3(24, 33), 256, dynSmem>>>(x, Wq, Wk, Wv, rot, mem_k, mem_v);
    k_dots<<<dim3(17, 16, 32), 256>>>(pre);
    k_mix1<<<BB*NNN, 512>>>(pre, preP);
    k_mix2<<<BB*NNN, 512>>>(post, postP);
    k_av<<<dim3(16, 32), 256>>>();
    k_outproj<<<dim3(8, 32), 256, dynSmem>>>(Wo, bo, out);
}

// round 13
// speedup vs baseline: 1.0894x; 1.0268x over previous
#include <cuda_runtime.h>
#include <cstdint>
#include <cfloat>
#include <math.h>

#define BB   2
#define NNN  2048
#define DIMM 1024
#define HHH  16
#define DHH  64
#define MMM  16
#define JJJ  2064   // M + N
#define J4   516    // JJJ/4
#define ROTD 32

// d_out layout (floats): out | pre | post
#define OFF_OUT  0
#define OFF_PRE  (BB*NNN*DIMM)
#define OFF_POST (OFF_PRE + BB*HHH*NNN*JJJ)

// ---- scratch (device globals; allocation-free rule) ----
__device__ float g_q  [BB*HHH*NNN*DHH];                 // (b,h,i,d)
__device__ float g_k  [BB*HHH*JJJ*DHH];                 // (b,h,j,d)
__device__ float g_vT [BB*HHH*DHH*JJJ];                 // (b,h,d,j)
__device__ float g_attn2[(size_t)BB*HHH*NNN*JJJ];       // mixed logits, then post-mixed attn
__device__ float g_oh [BB*NNN*HHH*DHH];                 // (b,i, h*64+d)
__device__ float g_stat_m  [BB*HHH*NNN];
__device__ float g_stat_inv[BB*HHH*NNN];

// ---------------- tf32 mma helpers ----------------
__device__ __forceinline__ uint32_t f2tf(float f) {
    uint32_t u; asm("cvt.rna.tf32.f32 %0, %1;" : "=r"(u) : "f"(f)); return u;
}
__device__ __forceinline__ uint4 f2tf4(float4 v) {
    uint4 u; u.x = f2tf(v.x); u.y = f2tf(v.y); u.z = f2tf(v.z); u.w = f2tf(v.w); return u;
}
__device__ __forceinline__ void mma8(float c[4], const uint32_t a[4], uint32_t b0, uint32_t b1) {
    asm volatile(
        "mma.sync.aligned.m16n8k8.row.col.f32.tf32.tf32.f32 "
        "{%0,%1,%2,%3},{%4,%5,%6,%7},{%8,%9},{%0,%1,%2,%3};"
        : "+f"(c[0]), "+f"(c[1]), "+f"(c[2]), "+f"(c[3])
        : "r"(a[0]), "r"(a[1]), "r"(a[2]), "r"(a[3]), "r"(b0), "r"(b1));
}

// Warp computes a 32x(NT*8) C tile; smem tiles hold PRE-CONVERTED tf32 bits.
template<int S, int NT>
__device__ __forceinline__ void warp_mma(const uint32_t* As, const uint32_t* Bs,
                                         int mw, int nw, int kc, int lane,
                                         float acc[2][NT][4]) {
    const int r = lane >> 2, q = lane & 3;
    for (int k0 = 0; k0 < kc; k0 += 8) {
        uint32_t a[2][4];
#pragma unroll
        for (int mt = 0; mt < 2; mt++) {
            const uint32_t* p = As + (mw + mt*16 + r) * S + k0 + q;
            a[mt][0] = p[0];
            a[mt][1] = p[8*S];
            a[mt][2] = p[4];
            a[mt][3] = p[8*S + 4];
        }
#pragma unroll
        for (int nt = 0; nt < NT; nt++) {
            const uint32_t* p = Bs + (nw + nt*8 + r) * S + k0 + q;
            uint32_t b0 = p[0], b1 = p[4];
            mma8(acc[0][nt], a[0], b0, b1);
            mma8(acc[1][nt], a[1], b0, b1);
        }
    }
}

#define TILE_U (128*36)   // one 128x32 tile (S=36) in uint32

// ---------------- K1: QKV projection + rotary (+ memfill fold), double-buffered ----------------
__global__ __launch_bounds__(256, 2)
void k_qkv(const float* __restrict__ x,
           const float* __restrict__ Wq, const float* __restrict__ Wk,
           const float* __restrict__ Wv, const float* __restrict__ rot,
           const float* __restrict__ mem_k, const float* __restrict__ mem_v) {
    extern __shared__ uint32_t smq[];
    uint32_t* Asb = smq;                 // [2][TILE_U]
    uint32_t* Bsb = smq + 2*TILE_U;      // [2][TILE_U]
    const int tid = threadIdx.x, lane = tid & 31, w = tid >> 5;

    if (blockIdx.y == 32) {
        const int total = BB*HHH*MMM*DHH;     // 32768
        for (int idx = blockIdx.x*256 + tid; idx < total; idx += 24*256) {
            int d = idx & 63, j = (idx >> 6) & 15, bh = idx >> 10;
            int h = bh & 15;
            g_k [((size_t)bh*JJJ + j)*DHH + d] = mem_k[(h*MMM + j)*DHH + d];
            g_vT[((size_t)bh*DHH + d)*JJJ + j] = mem_v[(h*MMM + j)*DHH + d];
        }
        return;
    }

    const int mbase = blockIdx.y * 128;
    const int ntile = blockIdx.x;
    const int which = ntile >> 3;                  // 0=q 1=k 2=v
    const float* W = (which == 0) ? Wq : (which == 1 ? Wk : Wv);
    const int nlocal = (ntile & 7) * 128;
    const int mw = (w >> 1)*32, nwarp = (w & 1)*64;
    const int h = ((ntile & 7) << 1) + (w & 1);

    float acc[2][8][4];
#pragma unroll
    for (int a = 0; a < 2; a++)
#pragma unroll
        for (int b = 0; b < 8; b++)
#pragma unroll
            for (int c = 0; c < 4; c++) acc[a][b][c] = 0.f;

    // preload stage 0 (kc = 0)
#pragma unroll
    for (int t = 0; t < 4; t++) {
        int idx = tid + t*256;
        int row = idx >> 3, col4 = (idx & 7) * 4;
        float4 va = *(const float4*)&x[(size_t)(mbase + row)*1024 + col4];
        *(uint4*)&Asb[row*36 + col4] = f2tf4(va);
        float4 vb = *(const float4*)&W[(size_t)(nlocal + row)*1024 + col4];
        *(uint4*)&Bsb[row*36 + col4] = f2tf4(vb);
    }
    __syncthreads();

    int s = 0;
    for (int kc = 0; kc < 1024; kc += 32) {
        float4 pa[4], pb[4];
        const bool more = (kc + 32 < 1024);
        if (more) {
#pragma unroll
            for (int t = 0; t < 4; t++) {
                int idx = tid + t*256;
                int row = idx >> 3, col4 = (idx & 7) * 4;
                pa[t] = *(const float4*)&x[(size_t)(mbase + row)*1024 + kc + 32 + col4];
                pb[t] = *(const float4*)&W[(size_t)(nlocal + row)*1024 + kc + 32 + col4];
            }
        }
        warp_mma<36, 8>(Asb + s*TILE_U, Bsb + s*TILE_U, mw, nwarp, 32, lane, acc);
        if (more) {
            uint32_t* An = Asb + (s ^ 1)*TILE_U;
            uint32_t* Bn = Bsb + (s ^ 1)*TILE_U;
#pragma unroll
            for (int t = 0; t < 4; t++) {
                int idx = tid + t*256;
                int row = idx >> 3, col4 = (idx & 7) * 4;
                *(uint4*)&An[row*36 + col4] = f2tf4(pa[t]);
                *(uint4*)&Bn[row*36 + col4] = f2tf4(pb[t]);
            }
        }
        __syncthreads();
        s ^= 1;
    }

    const int r = lane >> 2, q = lane & 3;

#pragma unroll
    for (int mt = 0; mt < 2; mt++) {
#pragma unroll
        for (int ci = 0; ci < 4; ci++) {
            int row = mbase + mw + mt*16 + r + ((ci & 2) ? 8 : 0);
            int b = row >> 11, i = row & 2047;
            if (which < 2) {
#pragma unroll
                for (int nt = 0; nt < 2; nt++) {
                    int d = nt*8 + 2*q + (ci & 1);
                    float lo = acc[mt][nt][ci];
                    float hi = acc[mt][nt + 2][ci];
                    float ang = rot[i*ROTD + d];
                    float cs, sn;
                    __sincosf(ang, &sn, &cs);
                    acc[mt][nt][ci]     = lo*cs - hi*sn;
                    acc[mt][nt + 2][ci] = hi*cs + lo*sn;
                }
            }
#pragma unroll
            for (int nt = 0; nt < 8; nt++) {
                int d = nt*8 + 2*q + (ci & 1);
                float v = acc[mt][nt][ci];
                size_t bh = (size_t)(b*16 + h);
                if (which == 0)      g_q [(bh*NNN + i)*DHH + d] = v;
                else if (which == 1) g_k [(bh*JJJ + i + 16)*DHH + d] = v;
                else                 g_vT[(bh*DHH + d)*JJJ + (i + 16)] = v;
            }
        }
    }
}

// ---------------- K2: dots = scale * q @ k^T -> pre ----------------
__global__ __launch_bounds__(256)
void k_dots(float* __restrict__ pre) {
    __shared__ uint32_t As[128*36];
    __shared__ uint32_t Bs[128*36];
    const int tid = threadIdx.x, lane = tid & 31, w = tid >> 5;
    const int bh = blockIdx.z;
    const int mbase = blockIdx.y * 128;
    const int jbase = blockIdx.x * 128;
    const int mw = (w >> 1)*32, nwarp = (w & 1)*64;

    float acc[2][8][4];
#pragma unroll
    for (int a = 0; a < 2; a++)
#pragma unroll
        for (int b = 0; b < 8; b++)
#pragma unroll
            for (int c = 0; c < 4; c++) acc[a][b][c] = 0.f;

    for (int kc = 0; kc < 64; kc += 32) {
#pragma unroll
        for (int t = 0; t < 4; t++) {
            int idx = tid + t*256;
            int row = idx >> 3, col4 = (idx & 7) * 4;
            float4 va = *(const float4*)&g_q[((size_t)bh*NNN + mbase + row)*DHH + kc + col4];
            *(uint4*)&As[row*36 + col4] = f2tf4(va);
            int j = jbase + row;
            float4 vb = (j < JJJ)
                ? *(const float4*)&g_k[((size_t)bh*JJJ + j)*DHH + kc + col4]
                : make_float4(0.f, 0.f, 0.f, 0.f);
            *(uint4*)&Bs[row*36 + col4] = f2tf4(vb);
        }
        __syncthreads();
        warp_mma<36, 8>(As, Bs, mw, nwarp, 32, lane, acc);
        __syncthreads();
    }

    const int r = lane >> 2, q = lane & 3;
#pragma unroll
    for (int mt = 0; mt < 2; mt++)
#pragma unroll
        for (int ci = 0; ci < 4; ci++) {
            int row = mbase + mw + mt*16 + r + ((ci & 2) ? 8 : 0);
#pragma unroll
            for (int nt = 0; nt < 8; nt++) {
                int j = jbase + nwarp + nt*8 + 2*q + (ci & 1);
                if (j < JJJ)
                    pre[((size_t)bh*NNN + row)*JJJ + j] = acc[mt][nt][ci] * 0.125f;
            }
        }
}

// ---------------- M1: mix1 + online softmax stats ----------------
__global__ __launch_bounds__(512, 2)
void k_mix1(const float* __restrict__ pre, const float* __restrict__ preP) {
    __shared__ float4 sC[16][128];
    const int bx = blockIdx.x;
    const int b = bx >> 11, i = bx & 2047;
    const int tid = threadIdx.x, lane = tid & 31, w = tid >> 5;
    const int nvalid = i + 17;
    const int nv4 = (nvalid + 3) >> 2;

    float pk[16];
#pragma unroll
    for (int h = 0; h < 16; h++) pk[h] = __ldg(&preP[h*16 + w]);

    const float4* src = (const float4*)&pre[(((size_t)(b*16 + w))*NNN + i)*JJJ];
    float4* dst = (float4*)&g_attn2[(((size_t)(b*16 + w))*NNN + i)*JJJ];

    float m = -FLT_MAX, s = 0.f;

    for (int base = 0; base < nv4; base += 128) {
        int c4 = min(128, nv4 - base);
        for (int c = lane; c < c4; c += 32) sC[w][c] = src[base + c];
        __syncthreads();
        for (int c = lane; c < c4; c += 32) {
            float4 mx = make_float4(0.f, 0.f, 0.f, 0.f);
#pragma unroll
            for (int h = 0; h < 16; h++) {
                float4 d = sC[h][c];
                mx.x += d.x*pk[h]; mx.y += d.y*pk[h];
                mx.z += d.z*pk[h]; mx.w += d.w*pk[h];
            }
            dst[base + c] = mx;
            int j0 = 4*(base + c);
            float v0 = mx.x;
            float v1 = (j0 + 1 < nvalid) ? mx.y : -FLT_MAX;
            float v2 = (j0 + 2 < nvalid) ? mx.z : -FLT_MAX;
            float v3 = (j0 + 3 < nvalid) ? mx.w : -FLT_MAX;
            float cm = fmaxf(fmaxf(v0, v1), fmaxf(v2, v3));
            float mn = fmaxf(m, cm);
            float add = __expf(v0 - mn) + __expf(v1 - mn) + __expf(v2 - mn) + __expf(v3 - mn);
            s = s*__expf(m - mn) + add;
            m = mn;
        }
        __syncthreads();
    }

#pragma unroll
    for (int o = 16; o > 0; o >>= 1) {
        float om = __shfl_xor_sync(0xffffffffu, m, o);
        float os = __shfl_xor_sync(0xffffffffu, s, o);
        float mn = fmaxf(m, om);
        s = s*__expf(m - mn) + os*__expf(om - mn);
        m = mn;
    }
    if (lane == 0) {
        g_stat_m  [(size_t)(b*16 + w)*NNN + i] = m;
        g_stat_inv[(size_t)(b*16 + w)*NNN + i] = 1.0f / s;
    }
}

// ---------------- M2: exp + post + mix2 -> attn2 (column-split, high-occ) ----------------
// grid (4096, 2): y = column half. block 256 = 8 warps; warp handles heads {w, w+8}
// in 2 passes. smem 16.5KB -> 6 CTAs/SM target.
__global__ __launch_bounds__(256, 6)
void k_mix2(float* __restrict__ post, const float* __restrict__ postP) {
    __shared__ float4 sC[16][64];
    __shared__ float sM[16];
    __shared__ float sInv[16];
    const int bx = blockIdx.x;
    const int b = bx >> 11, i = bx & 2047;
    const int half = blockIdx.y;
    const int tid = threadIdx.x, lane = tid & 31, w = tid >> 5;
    const int nvalid = i + 17;
    const int nv4 = (nvalid + 3) >> 2;

    if (tid < 16) {
        sM[tid]   = g_stat_m  [(size_t)(b*16 + tid)*NNN + i];
        sInv[tid] = g_stat_inv[(size_t)(b*16 + tid)*NNN + i];
    }
    __syncthreads();

    const int mid = (nv4 + 1) >> 1;
    const int c0 = half ? mid : 0;
    const int c1 = half ? nv4 : mid;

    const size_t rowStride = (size_t)NNN * JJJ;
    float* mbase0 = g_attn2 + (((size_t)(b*16))*NNN + i)*JJJ;
    float* pbase0 = post    + (((size_t)(b*16))*NNN + i)*JJJ;

    for (int base = c0; base < c1; base += 64) {
        const int cnt = min(64, c1 - base);
        // exp + post for heads w and w+8
#pragma unroll
        for (int pass = 0; pass < 2; pass++) {
            const int hh = w + pass*8;
            const float mm = sM[hh];
            const float inv = sInv[hh];
            float4* mrow = (float4*)(mbase0 + hh*rowStride);
            float4* prow = (float4*)(pbase0 + hh*rowStride);
            for (int c = lane; c < cnt; c += 32) {
                const int gc = base + c;
                float4 v = mrow[gc];
                const int j0 = 4*gc;
                float4 e;
                e.x = __expf(v.x - mm);
                e.y = (j0 + 1 < nvalid) ? __expf(v.y - mm) : 0.f;
                e.z = (j0 + 2 < nvalid) ? __expf(v.z - mm) : 0.f;
                e.w = (j0 + 3 < nvalid) ? __expf(v.w - mm) : 0.f;
                sC[hh][c] = e;
                prow[gc] = make_float4(e.x*inv, e.y*inv, e.z*inv, e.w*inv);
            }
        }
        __syncthreads();
        // gather for out-heads w and w+8
#pragma unroll
        for (int pass = 0; pass < 2; pass++) {
            const int oh = w + pass*8;
            float ck[16];
#pragma unroll
            for (int k = 0; k < 16; k++) ck[k] = sInv[k] * __ldg(&postP[k*16 + oh]);
            float4* orow = (float4*)(mbase0 + oh*rowStride);
            for (int c = lane; c < cnt; c += 32) {
                float4 acc = make_float4(0.f, 0.f, 0.f, 0.f);
#pragma unroll
                for (int k = 0; k < 16; k++) {
                    float4 d = sC[k][c];
                    acc.x += d.x*ck[k]; acc.y += d.y*ck[k];
                    acc.z += d.z*ck[k]; acc.w += d.w*ck[k];
                }
                orow[base + c] = acc;
            }
        }
        __syncthreads();
    }

    // tails (half==1 only): post zeros to JJJ; attn2 zeros to k_av's read bound
    if (half == 1) {
        const float4 z4 = make_float4(0.f, 0.f, 0.f, 0.f);
        int kcend = ((((i >> 7) << 7) + 144 + 47) / 48) * 48;
        if (kcend > JJJ) kcend = JJJ;
        const int kc4 = kcend >> 2;
#pragma unroll 1
        for (int h = 0; h < 16; h++) {
            float4* pp = (float4*)(pbase0 + h*rowStride);
            for (int c = nv4 + tid; c < J4; c += 256) pp[c] = z4;
            float4* aa = (float4*)(mbase0 + h*rowStride);
            for (int c = nv4 + tid; c < kc4; c += 256) aa[c] = z4;
        }
    }
}

// ---------------- K4: out_heads = attn2 @ v ----------------
__global__ __launch_bounds__(256)
void k_av() {
    __shared__ uint32_t As[128*52];
    __shared__ uint32_t Bs[64*52];
    const int tid = threadIdx.x, lane = tid & 31, w = tid >> 5;
    const int mbase = blockIdx.x * 128;
    const int bh = blockIdx.y;
    const int b = bh >> 4, h = bh & 15;
    const int mw = (w >> 1)*32, nw = (w & 1)*32;

    float acc[2][4][4];
#pragma unroll
    for (int a = 0; a < 2; a++)
#pragma unroll
        for (int bb = 0; bb < 4; bb++)
#pragma unroll
            for (int c = 0; c < 4; c++) acc[a][bb][c] = 0.f;

    const float* Abase = &g_attn2[((size_t)bh*NNN + mbase)*JJJ];
    const float* Bbase = &g_vT[(size_t)bh*DHH*JJJ];

    int kcend = mbase + 144;
    kcend = ((kcend + 47) / 48) * 48;
    if (kcend > JJJ) kcend = JJJ;

    for (int kc = 0; kc < kcend; kc += 48) {
#pragma unroll
        for (int t = 0; t < 6; t++) {
            int idx = tid + t*256;
            int row = idx / 12, col4 = (idx % 12) * 4;
            float4 va = *(const float4*)&Abase[(size_t)row*JJJ + kc + col4];
            *(uint4*)&As[row*52 + col4] = f2tf4(va);
        }
#pragma unroll
        for (int t = 0; t < 3; t++) {
            int idx = tid + t*256;
            int row = idx / 12, col4 = (idx % 12) * 4;
            float4 vb = *(const float4*)&Bbase[(size_t)row*JJJ + kc + col4];
            *(uint4*)&Bs[row*52 + col4] = f2tf4(vb);
        }
        __syncthreads();
        warp_mma<52, 4>(As, Bs, mw, nw, 48, lane, acc);
        __syncthreads();
    }

    const int r = lane >> 2, q = lane & 3;
#pragma unroll
    for (int mt = 0; mt < 2; mt++)
#pragma unroll
        for (int ci = 0; ci < 4; ci++) {
            int row = mbase + mw + mt*16 + r + ((ci & 2) ? 8 : 0);
#pragma unroll
            for (int nt = 0; nt < 4; nt++) {
                int d = nw + nt*8 + 2*q + (ci & 1);
                g_oh[((size_t)(b*NNN + row))*DIMM + h*DHH + d] = acc[mt][nt][ci];
            }
        }
}

// ---------------- K5: out = oh @ Wo^T + bo, double-buffered ----------------
__global__ __launch_bounds__(256, 2)
void k_outproj(const float* __restrict__ Wo, const float* __restrict__ bo,
               float* __restrict__ out) {
    extern __shared__ uint32_t smo[];
    uint32_t* Asb = smo;
    uint32_t* Bsb = smo + 2*TILE_U;
    const int tid = threadIdx.x, lane = tid & 31, w = tid >> 5;
    const int mbase = blockIdx.y * 128;
    const int nbase = blockIdx.x * 128;
    const int mw = (w >> 1)*32, nwarp = (w & 1)*64;

    float acc[2][8][4];
#pragma unroll
    for (int a = 0; a < 2; a++)
#pragma unroll
        for (int b = 0; b < 8; b++)
#pragma unroll
            for (int c = 0; c < 4; c++) acc[a][b][c] = 0.f;

    // preload stage 0
#pragma unroll
    for (int t = 0; t < 4; t++) {
        int idx = tid + t*256;
        int row = idx >> 3, col4 = (idx & 7) * 4;
        float4 va = *(const float4*)&g_oh[(size_t)(mbase + row)*1024 + col4];
        *(uint4*)&Asb[row*36 + col4] = f2tf4(va);
        float4 vb = *(const float4*)&Wo[(size_t)(nbase + row)*1024 + col4];
        *(uint4*)&Bsb[row*36 + col4] = f2tf4(vb);
    }
    __syncthreads();

    int s = 0;
    for (int kc = 0; kc < 1024; kc += 32) {
        float4 pa[4], pb[4];
        const bool more = (kc + 32 < 1024);
        if (more) {
#pragma unroll
            for (int t = 0; t < 4; t++) {
                int idx = tid + t*256;
                int row = idx >> 3, col4 = (idx & 7) * 4;
                pa[t] = *(const float4*)&g_oh[(size_t)(mbase + row)*1024 + kc + 32 + col4];
                pb[t] = *(const float4*)&Wo[(size_t)(nbase + row)*1024 + kc + 32 + col4];
            }
        }
        warp_mma<36, 8>(Asb + s*TILE_U, Bsb + s*TILE_U, mw, nwarp, 32, lane, acc);
        if (more) {
            uint32_t* An = Asb + (s ^ 1)*TILE_U;
            uint32_t* Bn = Bsb + (s ^ 1)*TILE_U;
#pragma unroll
            for (int t = 0; t < 4; t++) {
                int idx = tid + t*256;
                int row = idx >> 3, col4 = (idx & 7) * 4;
                *(uint4*)&An[row*36 + col4] = f2tf4(pa[t]);
                *(uint4*)&Bn[row*36 + col4] = f2tf4(pb[t]);
            }
        }
        __syncthreads();
        s ^= 1;
    }

    const int r = lane >> 2, q = lane & 3;
#pragma unroll
    for (int mt = 0; mt < 2; mt++)
#pragma unroll
        for (int ci = 0; ci < 4; ci++) {
            int row = mbase + mw + mt*16 + r + ((ci & 2) ? 8 : 0);
#pragma unroll
            for (int nt = 0; nt < 8; nt++) {
                int col = nbase + nwarp + nt*8 + 2*q + (ci & 1);
                out[(size_t)row*1024 + col] = acc[mt][nt][ci] + bo[col];
            }
        }
}

// ---------------- launch ----------------
extern "C" void kernel_launch(void* const* d_in, const int* in_sizes, int n_in,
                              void* d_out, int out_size) {
    const float* x     = (const float*)d_in[0];
    const float* rot   = (const float*)d_in[1];
    const float* Wq    = (const float*)d_in[2];
    const float* Wk    = (const float*)d_in[3];
    const float* Wv    = (const float*)d_in[4];
    const float* mem_k = (const float*)d_in[5];
    const float* mem_v = (const float*)d_in[6];
    const float* preP  = (const float*)d_in[7];
    const float* postP = (const float*)d_in[8];
    const float* Wo    = (const float*)d_in[9];
    const float* bo    = (const float*)d_in[10];

    float* out  = (float*)d_out;
    float* pre  = out + OFF_PRE;
    float* post = out + OFF_POST;

    const int dynSmem = 4 * TILE_U * sizeof(uint32_t);   // 73728 bytes
    static bool attrDone = false;
    if (!attrDone) {
        cudaFuncSetAttribute(k_qkv, cudaFuncAttributeMaxDynamicSharedMemorySize, dynSmem);
        cudaFuncSetAttribute(k_outproj, cudaFuncAttributeMaxDynamicSharedMemorySize, dynSmem);
        attrDone = true;
    }

    k_qkv<<<dim3(24, 33), 256, dynSmem>>>(x, Wq, Wk, Wv, rot, mem_k, mem_v);
    k_dots<<<dim3(17, 16, 32), 256>>>(pre);
    k_mix1<<<BB*NNN, 512>>>(pre, preP);
    k_mix2<<<dim3(BB*NNN, 2), 256>>>(post, postP);
    k_av<<<dim3(16, 32), 256>>>();
    k_outproj<<<dim3(8, 32), 256, dynSmem>>>(Wo, bo, out);
}